// round 2
// baseline (speedup 1.0000x reference)
#include <cuda_runtime.h>
#include <math.h>

// Problem constants
#define BATCH   2
#define TSEQ    2048
#define CDIM    1024
#define NHEAD   16
#define HS      64
#define M_GEMM  (BATCH*TSEQ)   // 4096
#define N_GEMM  (3*CDIM)       // 3072
#define K_GEMM  CDIM           // 1024

// Scratch for qkv = x @ W + b  : [4096, 3072] fp32 (48 MB, static device bss)
__device__ float g_qkv[(size_t)M_GEMM * N_GEMM];

// ---------------------------------------------------------------------------
// Kernel A: SGEMM  qkv[M,N] = X[M,K] @ W[K,N] + bias[N]
// 128x128 tile, BK=16, 256 threads, 8x8 microtile.
// Register-staged double buffering: global loads for tile t+1 are issued
// before the compute phase of tile t, hiding L2/DRAM latency behind FMAs.
// ---------------------------------------------------------------------------
__global__ __launch_bounds__(256) void qkv_gemm_kernel(
    const float* __restrict__ A, const float* __restrict__ W,
    const float* __restrict__ bias)
{
    constexpr int BM = 128, BN = 128, BK = 16;
    __shared__ float As[BK][132];   // transposed A tile, padded
    __shared__ float Bs[BK][132];   // B tile, padded

    const int tid = threadIdx.x;
    const int tx  = tid & 15;       // 0..15
    const int ty  = tid >> 4;       // 0..15
    const int brow = blockIdx.y;
    const int bcol = blockIdx.x;

    const float* Ab = A + (size_t)brow * BM * K_GEMM;
    const float* Wb = W + bcol * BN;

    // load indices
    const int aRow = tid >> 2;          // 0..63
    const int aCol = (tid & 3) << 2;    // 0,4,8,12
    const int bRow = tid >> 5;          // 0..7
    const int bCol = (tid & 31) << 2;   // 0..124

    float acc[8][8];
#pragma unroll
    for (int i = 0; i < 8; i++)
#pragma unroll
        for (int j = 0; j < 8; j++) acc[i][j] = 0.0f;

    float4 aReg[2], bReg[2];

    // prologue: load tile 0 into registers, then smem
#pragma unroll
    for (int it = 0; it < 2; it++) {
        const int r  = aRow + it * 64;
        const int br = bRow + it * 8;
        aReg[it] = *(const float4*)(Ab + (size_t)r * K_GEMM + aCol);
        bReg[it] = *(const float4*)(Wb + (size_t)br * N_GEMM + bCol);
    }
#pragma unroll
    for (int it = 0; it < 2; it++) {
        const int r  = aRow + it * 64;
        const int br = bRow + it * 8;
        As[aCol + 0][r] = aReg[it].x;
        As[aCol + 1][r] = aReg[it].y;
        As[aCol + 2][r] = aReg[it].z;
        As[aCol + 3][r] = aReg[it].w;
        *(float4*)(&Bs[br][bCol]) = bReg[it];
    }
    __syncthreads();

    for (int k0 = 0; k0 < K_GEMM; k0 += BK) {
        const bool has_next = (k0 + BK) < K_GEMM;
        // issue next tile's global loads early (latency hidden by compute)
        if (has_next) {
#pragma unroll
            for (int it = 0; it < 2; it++) {
                const int r  = aRow + it * 64;
                const int br = bRow + it * 8;
                aReg[it] = *(const float4*)(Ab + (size_t)r * K_GEMM + (k0 + BK) + aCol);
                bReg[it] = *(const float4*)(Wb + (size_t)(k0 + BK + br) * N_GEMM + bCol);
            }
        }

#pragma unroll
        for (int k = 0; k < BK; k++) {
            float rM[8], rN[8];
            *(float4*)(rM)     = *(const float4*)(&As[k][ty * 8]);
            *(float4*)(rM + 4) = *(const float4*)(&As[k][ty * 8 + 4]);
            *(float4*)(rN)     = *(const float4*)(&Bs[k][tx * 4]);
            *(float4*)(rN + 4) = *(const float4*)(&Bs[k][64 + tx * 4]);
#pragma unroll
            for (int i = 0; i < 8; i++)
#pragma unroll
                for (int j = 0; j < 8; j++)
                    acc[i][j] = fmaf(rM[i], rN[j], acc[i][j]);
        }
        __syncthreads();

        if (has_next) {
#pragma unroll
            for (int it = 0; it < 2; it++) {
                const int r  = aRow + it * 64;
                const int br = bRow + it * 8;
                As[aCol + 0][r] = aReg[it].x;
                As[aCol + 1][r] = aReg[it].y;
                As[aCol + 2][r] = aReg[it].z;
                As[aCol + 3][r] = aReg[it].w;
                *(float4*)(&Bs[br][bCol]) = bReg[it];
            }
            __syncthreads();
        }
    }

    // epilogue with bias
    const int rowBase = brow * BM + ty * 8;
    const int col0 = bcol * BN + tx * 4;
    const int col1 = col0 + 64;
    const float4 b0 = *(const float4*)(bias + col0);
    const float4 b1 = *(const float4*)(bias + col1);
#pragma unroll
    for (int i = 0; i < 8; i++) {
        float4 r0, r1;
        r0.x = acc[i][0] + b0.x; r0.y = acc[i][1] + b0.y;
        r0.z = acc[i][2] + b0.z; r0.w = acc[i][3] + b0.w;
        r1.x = acc[i][4] + b1.x; r1.y = acc[i][5] + b1.y;
        r1.z = acc[i][6] + b1.z; r1.w = acc[i][7] + b1.w;
        const size_t ro = (size_t)(rowBase + i) * N_GEMM;
        *(float4*)(g_qkv + ro + col0) = r0;
        *(float4*)(g_qkv + ro + col1) = r1;
    }
}

// ---------------------------------------------------------------------------
// Kernel B: causal flash attention, fp32 CUDA cores.
// grid = (T/64, NH, B), 256 threads.
// Thread (tx,ty): S rows 4ty+i, S cols tx+16j ; O rows 4ty+i, O cols 4tx+j.
// ---------------------------------------------------------------------------
#define BM_A 64
#define BN_A 64
#define QPAD 68     // 64+4 pad keeps all hot LDS paths <=2-way

// dyn smem layout (floats): Qs[64][68], Ks[64][68], Vs[64][64], Ps[64][68]
#define ATTN_SMEM_FLOATS (64*QPAD*3 + 64*64)
#define ATTN_SMEM_BYTES  (ATTN_SMEM_FLOATS * 4)

__global__ __launch_bounds__(256) void attn_kernel(float* __restrict__ out)
{
    extern __shared__ float sm[];
    float* Qs = sm;                    // 64*68
    float* Ks = Qs + 64 * QPAD;        // 64*68
    float* Vs = Ks + 64 * QPAD;        // 64*64
    float* Ps = Vs + 64 * 64;          // 64*68

    const int qb = blockIdx.x;
    const int h  = blockIdx.y;
    const int b  = blockIdx.z;
    const int tid = threadIdx.x;
    const int tx = tid & 15;
    const int ty = tid >> 4;

    const int q0 = qb * BM_A;
    const size_t base = (size_t)b * TSEQ * 3 * CDIM + (size_t)h * HS;
    const float* qkv = g_qkv;

    // load Q tile: 64 rows x 64 floats = 1024 float4, 4 per thread
#pragma unroll
    for (int it = 0; it < 4; it++) {
        const int idx = tid + it * 256;
        const int r  = idx >> 4;
        const int c4 = (idx & 15) << 2;
        float4 v = *(const float4*)(qkv + base + (size_t)(q0 + r) * (3 * CDIM) + c4);
        *(float4*)(Qs + r * QPAD + c4) = v;
    }

    float O[4][4];
#pragma unroll
    for (int i = 0; i < 4; i++)
#pragma unroll
        for (int j = 0; j < 4; j++) O[i][j] = 0.0f;
    float mrow[4], lrow[4];
#pragma unroll
    for (int i = 0; i < 4; i++) { mrow[i] = -INFINITY; lrow[i] = 0.0f; }

    const float scale = 0.125f;  // 1/sqrt(64)

    for (int kb = 0; kb <= qb; kb++) {
        const int k0 = kb * BN_A;
        __syncthreads();   // protect Ks/Vs/Ps from previous iteration
        // load K and V tiles
#pragma unroll
        for (int it = 0; it < 4; it++) {
            const int idx = tid + it * 256;
            const int r  = idx >> 4;
            const int c4 = (idx & 15) << 2;
            const size_t grow = base + (size_t)(k0 + r) * (3 * CDIM);
            *(float4*)(Ks + r * QPAD + c4) = *(const float4*)(qkv + grow + CDIM + c4);
            *(float4*)(Vs + r * 64 + c4)   = *(const float4*)(qkv + grow + 2 * CDIM + c4);
        }
        __syncthreads();

        // S = Q K^T (rows 4ty+i, cols tx+16j)
        float S[4][4];
#pragma unroll
        for (int i = 0; i < 4; i++)
#pragma unroll
            for (int j = 0; j < 4; j++) S[i][j] = 0.0f;

#pragma unroll
        for (int d = 0; d < 64; d += 4) {
            float4 qv[4], kv[4];
#pragma unroll
            for (int i = 0; i < 4; i++)
                qv[i] = *(const float4*)(Qs + (4 * ty + i) * QPAD + d);
#pragma unroll
            for (int j = 0; j < 4; j++)
                kv[j] = *(const float4*)(Ks + (tx + 16 * j) * QPAD + d);
#pragma unroll
            for (int i = 0; i < 4; i++)
#pragma unroll
                for (int j = 0; j < 4; j++) {
                    S[i][j] = fmaf(qv[i].x, kv[j].x, S[i][j]);
                    S[i][j] = fmaf(qv[i].y, kv[j].y, S[i][j]);
                    S[i][j] = fmaf(qv[i].z, kv[j].z, S[i][j]);
                    S[i][j] = fmaf(qv[i].w, kv[j].w, S[i][j]);
                }
        }

        // scale + causal mask (only needed on the diagonal block)
        if (kb == qb) {
#pragma unroll
            for (int i = 0; i < 4; i++)
#pragma unroll
                for (int j = 0; j < 4; j++) {
                    if (tx + 16 * j > 4 * ty + i) S[i][j] = -INFINITY;
                    else                          S[i][j] *= scale;
                }
        } else {
#pragma unroll
            for (int i = 0; i < 4; i++)
#pragma unroll
                for (int j = 0; j < 4; j++) S[i][j] *= scale;
        }

        // online softmax per row (row shared by 16 tx-lanes)
#pragma unroll
        for (int i = 0; i < 4; i++) {
            float mx = fmaxf(fmaxf(S[i][0], S[i][1]), fmaxf(S[i][2], S[i][3]));
#pragma unroll
            for (int off = 8; off >= 1; off >>= 1)
                mx = fmaxf(mx, __shfl_xor_sync(0xffffffffu, mx, off));
            const float mnew  = fmaxf(mrow[i], mx);
            const float alpha = __expf(mrow[i] - mnew);
            float ls = 0.0f;
#pragma unroll
            for (int j = 0; j < 4; j++) {
                const float p = __expf(S[i][j] - mnew);
                S[i][j] = p;
                ls += p;
            }
#pragma unroll
            for (int off = 8; off >= 1; off >>= 1)
                ls += __shfl_xor_sync(0xffffffffu, ls, off);
            lrow[i] = lrow[i] * alpha + ls;
            mrow[i] = mnew;
#pragma unroll
            for (int j = 0; j < 4; j++) O[i][j] *= alpha;
            // write probabilities to smem
#pragma unroll
            for (int j = 0; j < 4; j++)
                Ps[(4 * ty + i) * QPAD + tx + 16 * j] = S[i][j];
        }
        __syncthreads();

        // O += P @ V  (rows 4ty+i, cols 4tx+j)
#pragma unroll
        for (int n = 0; n < 64; n += 4) {
            float4 pv[4];
#pragma unroll
            for (int i = 0; i < 4; i++)
                pv[i] = *(const float4*)(Ps + (4 * ty + i) * QPAD + n);
            float p0[4] = {pv[0].x, pv[1].x, pv[2].x, pv[3].x};
            float p1[4] = {pv[0].y, pv[1].y, pv[2].y, pv[3].y};
            float p2[4] = {pv[0].z, pv[1].z, pv[2].z, pv[3].z};
            float p3[4] = {pv[0].w, pv[1].w, pv[2].w, pv[3].w};

            float4 vv;
            vv = *(const float4*)(Vs + (n + 0) * 64 + 4 * tx);
#pragma unroll
            for (int i = 0; i < 4; i++) {
                O[i][0] = fmaf(p0[i], vv.x, O[i][0]);
                O[i][1] = fmaf(p0[i], vv.y, O[i][1]);
                O[i][2] = fmaf(p0[i], vv.z, O[i][2]);
                O[i][3] = fmaf(p0[i], vv.w, O[i][3]);
            }
            vv = *(const float4*)(Vs + (n + 1) * 64 + 4 * tx);
#pragma unroll
            for (int i = 0; i < 4; i++) {
                O[i][0] = fmaf(p1[i], vv.x, O[i][0]);
                O[i][1] = fmaf(p1[i], vv.y, O[i][1]);
                O[i][2] = fmaf(p1[i], vv.z, O[i][2]);
                O[i][3] = fmaf(p1[i], vv.w, O[i][3]);
            }
            vv = *(const float4*)(Vs + (n + 2) * 64 + 4 * tx);
#pragma unroll
            for (int i = 0; i < 4; i++) {
                O[i][0] = fmaf(p2[i], vv.x, O[i][0]);
                O[i][1] = fmaf(p2[i], vv.y, O[i][1]);
                O[i][2] = fmaf(p2[i], vv.z, O[i][2]);
                O[i][3] = fmaf(p2[i], vv.w, O[i][3]);
            }
            vv = *(const float4*)(Vs + (n + 3) * 64 + 4 * tx);
#pragma unroll
            for (int i = 0; i < 4; i++) {
                O[i][0] = fmaf(p3[i], vv.x, O[i][0]);
                O[i][1] = fmaf(p3[i], vv.y, O[i][1]);
                O[i][2] = fmaf(p3[i], vv.z, O[i][2]);
                O[i][3] = fmaf(p3[i], vv.w, O[i][3]);
            }
        }
    }

    // epilogue: divide by l and store. out[b][t][h*64 + d]
#pragma unroll
    for (int i = 0; i < 4; i++) {
        const float inv = 1.0f / lrow[i];
        float4 r;
        r.x = O[i][0] * inv; r.y = O[i][1] * inv;
        r.z = O[i][2] * inv; r.w = O[i][3] * inv;
        const size_t row = (size_t)b * TSEQ + q0 + 4 * ty + i;
        *(float4*)(out + row * CDIM + h * HS + 4 * tx) = r;
    }
}

// ---------------------------------------------------------------------------
extern "C" void kernel_launch(void* const* d_in, const int* in_sizes, int n_in,
                              void* d_out, int out_size)
{
    const float* x    = (const float*)d_in[0];
    const float* W    = (const float*)d_in[1];
    const float* bias = (const float*)d_in[2];
    float* out = (float*)d_out;

    (void)in_sizes; (void)n_in; (void)out_size;

    cudaFuncSetAttribute(attn_kernel,
                         cudaFuncAttributeMaxDynamicSharedMemorySize,
                         ATTN_SMEM_BYTES);

    dim3 ggrid(N_GEMM / 128, M_GEMM / 128);   // (24, 32)
    qkv_gemm_kernel<<<ggrid, 256>>>(x, W, bias);

    dim3 agrid(TSEQ / BM_A, NHEAD, BATCH);    // (32, 16, 2)
    attn_kernel<<<agrid, 256, ATTN_SMEM_BYTES>>>(out);
}

// round 11
// speedup vs baseline: 1.2588x; 1.2588x over previous
#include <cuda_runtime.h>
#include <cuda_bf16.h>
#include <math.h>
#include <stdint.h>

// Problem constants
#define BATCH   2
#define TSEQ    2048
#define CDIM    1024
#define NHEAD   16
#define HS      64
#define M_GEMM  (BATCH*TSEQ)   // 4096
#define N_GEMM  (3*CDIM)       // 3072
#define K_GEMM  CDIM           // 1024
#define KSPLIT  (3*K_GEMM)     // 3072 (hi*hi + hi*lo + lo*hi concatenation)

// Static device scratch (no allocations allowed)
__device__ float         g_qkv [(size_t)M_GEMM * N_GEMM];   // 48 MB
__device__ __nv_bfloat16 g_Xhi [(size_t)M_GEMM * K_GEMM];   // 8 MB
__device__ __nv_bfloat16 g_Xlo [(size_t)M_GEMM * K_GEMM];   // 8 MB
__device__ __nv_bfloat16 g_Wthi[(size_t)N_GEMM * K_GEMM];   // 6 MB (transposed W, [n][k])
__device__ __nv_bfloat16 g_Wtlo[(size_t)N_GEMM * K_GEMM];   // 6 MB

// ---------------------------------------------------------------------------
// Base-target async-copy helpers (sm_80+; NOT 'a'-suffix gated)
// ---------------------------------------------------------------------------
#define CP_ASYNC16(smem_u32, gptr) \
    asm volatile("cp.async.cg.shared.global [%0], [%1], 16;" \
                 :: "r"(smem_u32), "l"(gptr) : "memory")
#define CP_COMMIT() asm volatile("cp.async.commit_group;" ::: "memory")
#define CP_WAIT(n)  asm volatile("cp.async.wait_group %0;" :: "n"(n) : "memory")

__device__ __forceinline__ void mma_16816_bf16(
    float* c, uint32_t a0, uint32_t a1, uint32_t a2, uint32_t a3,
    uint32_t b0, uint32_t b1)
{
    asm volatile(
        "mma.sync.aligned.m16n8k16.row.col.f32.bf16.bf16.f32 "
        "{%0,%1,%2,%3}, {%4,%5,%6,%7}, {%8,%9}, {%0,%1,%2,%3};"
        : "+f"(c[0]), "+f"(c[1]), "+f"(c[2]), "+f"(c[3])
        : "r"(a0), "r"(a1), "r"(a2), "r"(a3), "r"(b0), "r"(b1));
}

// ---------------------------------------------------------------------------
// Conversion kernels: fp32 -> bf16 hi/lo split (and W transpose)
// ---------------------------------------------------------------------------
__global__ __launch_bounds__(256) void split_x_kernel(const float* __restrict__ X)
{
    const int idx = blockIdx.x * blockDim.x + threadIdx.x;   // over n/4 float4s
    float4 v = ((const float4*)X)[idx];
    __nv_bfloat16 h0 = __float2bfloat16(v.x), h1 = __float2bfloat16(v.y);
    __nv_bfloat16 h2 = __float2bfloat16(v.z), h3 = __float2bfloat16(v.w);
    __nv_bfloat16 l0 = __float2bfloat16(v.x - __bfloat162float(h0));
    __nv_bfloat16 l1 = __float2bfloat16(v.y - __bfloat162float(h1));
    __nv_bfloat16 l2 = __float2bfloat16(v.z - __bfloat162float(h2));
    __nv_bfloat16 l3 = __float2bfloat16(v.w - __bfloat162float(h3));
    __nv_bfloat162 p;
    p.x = h0; p.y = h1; ((__nv_bfloat162*)g_Xhi)[2 * idx]     = p;
    p.x = h2; p.y = h3; ((__nv_bfloat162*)g_Xhi)[2 * idx + 1] = p;
    p.x = l0; p.y = l1; ((__nv_bfloat162*)g_Xlo)[2 * idx]     = p;
    p.x = l2; p.y = l3; ((__nv_bfloat162*)g_Xlo)[2 * idx + 1] = p;
}

__global__ __launch_bounds__(256) void split_w_kernel(const float* __restrict__ W)
{
    __shared__ float ts[32][33];
    const int n0 = blockIdx.x * 32, k0 = blockIdx.y * 32;
    const int tx = threadIdx.x, ty = threadIdx.y;   // (32, 8)
#pragma unroll
    for (int j = 0; j < 4; j++)
        ts[ty + j * 8][tx] = W[(size_t)(k0 + ty + j * 8) * N_GEMM + n0 + tx];
    __syncthreads();
#pragma unroll
    for (int j = 0; j < 4; j++) {
        const float v = ts[tx][ty + j * 8];
        const __nv_bfloat16 h = __float2bfloat16(v);
        const __nv_bfloat16 l = __float2bfloat16(v - __bfloat162float(h));
        const size_t o = (size_t)(n0 + ty + j * 8) * K_GEMM + k0 + tx;
        g_Wthi[o] = h;
        g_Wtlo[o] = l;
    }
}

// ---------------------------------------------------------------------------
// bf16 split GEMM via mma.sync (HMMA):
//   qkv[4096,3072] = A'[4096,3072k] @ B'[3072n,3072k]^T + bias
// Block 128x128, BK=32, 8 warps (2x4), warp tile 64x32, cp.async 3-stage.
// ---------------------------------------------------------------------------
#define BKC 32
#define NCHUNK (KSPLIT / BKC)   // 96
#define APAD 40                 // row stride in bf16 (conflict-free fragment loads)
#define NSTAGE 3

__global__ __launch_bounds__(256) void qkv_gemm_mma(const float* __restrict__ bias)
{
    __shared__ __align__(16) __nv_bfloat16 As[NSTAGE][128][APAD];
    __shared__ __align__(16) __nv_bfloat16 Bs[NSTAGE][128][APAD];

    const int tid  = threadIdx.x;
    const int warp = tid >> 5;
    const int lane = tid & 31;
    const int g    = lane >> 2;       // group id 0..7
    const int tg   = lane & 3;        // thread-in-group 0..3
    const int wm   = (warp >> 2) * 64;   // warp m-offset (0 or 64)
    const int wn   = (warp & 3) * 32;    // warp n-offset (0,32,64,96)
    const int brow = blockIdx.y;
    const int bcol = blockIdx.x;

    // global->smem load mapping: 2 iters, each thread one 16B (8 bf16) segment
    const int ldRow  = tid >> 2;        // 0..63
    const int ldCol8 = (tid & 3) * 8;   // 0,8,16,24 (bf16)

    float acc[4][4][4];
#pragma unroll
    for (int mi = 0; mi < 4; mi++)
#pragma unroll
        for (int ni = 0; ni < 4; ni++)
#pragma unroll
            for (int r = 0; r < 4; r++) acc[mi][ni][r] = 0.0f;

    const size_t aRowOff = (size_t)brow * 128 * K_GEMM;
    const size_t bRowOff = (size_t)bcol * 128 * K_GEMM;

    // tile loader: chunk c into stage s
    auto load_tile = [&](int c, int s) {
        const int kb  = c * BKC;
        const int reg = kb >> 10;        // which of the 3 K-regions
        const int ko  = kb & 1023;
        const __nv_bfloat16* Asrc = (reg == 2 ? g_Xlo  : g_Xhi ) + aRowOff + ko;
        const __nv_bfloat16* Bsrc = (reg == 1 ? g_Wtlo : g_Wthi) + bRowOff + ko;
#pragma unroll
        for (int it = 0; it < 2; it++) {
            const int r = ldRow + it * 64;
            CP_ASYNC16((uint32_t)__cvta_generic_to_shared(&As[s][r][ldCol8]),
                       Asrc + (size_t)r * K_GEMM + ldCol8);
            CP_ASYNC16((uint32_t)__cvta_generic_to_shared(&Bs[s][r][ldCol8]),
                       Bsrc + (size_t)r * K_GEMM + ldCol8);
        }
        CP_COMMIT();
    };

    // prologue: fill NSTAGE-1 stages
    load_tile(0, 0);
    load_tile(1, 1);

    for (int c = 0; c < NCHUNK; c++) {
        const int buf = c % NSTAGE;
        if (c + NSTAGE - 1 < NCHUNK) {
            load_tile(c + NSTAGE - 1, (c + NSTAGE - 1) % NSTAGE);
            CP_WAIT(NSTAGE - 1);   // tile c complete; up to 2 in flight
        } else if (c + 1 < NCHUNK) {
            CP_WAIT(1);
        } else {
            CP_WAIT(0);
        }
        __syncthreads();

#pragma unroll
        for (int ks = 0; ks < 2; ks++) {
            const int kc = tg * 2 + ks * 16;
            uint32_t a[4][4];
#pragma unroll
            for (int mi = 0; mi < 4; mi++) {
                const int r = wm + mi * 16 + g;
                a[mi][0] = *(const uint32_t*)&As[buf][r    ][kc];
                a[mi][1] = *(const uint32_t*)&As[buf][r + 8][kc];
                a[mi][2] = *(const uint32_t*)&As[buf][r    ][kc + 8];
                a[mi][3] = *(const uint32_t*)&As[buf][r + 8][kc + 8];
            }
            uint32_t b[4][2];
#pragma unroll
            for (int ni = 0; ni < 4; ni++) {
                const int r = wn + ni * 8 + g;
                b[ni][0] = *(const uint32_t*)&Bs[buf][r][kc];
                b[ni][1] = *(const uint32_t*)&Bs[buf][r][kc + 8];
            }
#pragma unroll
            for (int mi = 0; mi < 4; mi++)
#pragma unroll
                for (int ni = 0; ni < 4; ni++)
                    mma_16816_bf16(acc[mi][ni],
                                   a[mi][0], a[mi][1], a[mi][2], a[mi][3],
                                   b[ni][0], b[ni][1]);
        }
        __syncthreads();   // protect stage reuse by the next cp.async wave
    }

    // epilogue: acc -> g_qkv with bias
#pragma unroll
    for (int mi = 0; mi < 4; mi++) {
        const int row0 = brow * 128 + wm + mi * 16 + g;
#pragma unroll
        for (int ni = 0; ni < 4; ni++) {
            const int col0 = bcol * 128 + wn + ni * 8 + tg * 2;
            const float b0 = bias[col0], b1 = bias[col0 + 1];
            float2 v;
            v.x = acc[mi][ni][0] + b0;
            v.y = acc[mi][ni][1] + b1;
            *(float2*)(g_qkv + (size_t)row0 * N_GEMM + col0) = v;
            v.x = acc[mi][ni][2] + b0;
            v.y = acc[mi][ni][3] + b1;
            *(float2*)(g_qkv + (size_t)(row0 + 8) * N_GEMM + col0) = v;
        }
    }
}

// ---------------------------------------------------------------------------
// Kernel B: causal flash attention, fp32, 8x8 microtile (S) / 8x4 (O).
// BM=BN=128, 256 threads (tx 0..15, ty 0..15).
// Thread (tx,ty): S rows 8ty+i, S cols tx+16j ; O rows 8ty+i, O cols 4tx+j.
// Row softmax reduction across the 16 tx-lanes (half-warp), as before.
// ---------------------------------------------------------------------------
#define BM_A 128
#define BN_A 128
#define QPAD 68      // Q/K/V row stride (64+4)
#define PPAD 132     // P row stride (128+4)

#define ATTN_SMEM_FLOATS (128*QPAD*3 + 128*PPAD)
#define ATTN_SMEM_BYTES  (ATTN_SMEM_FLOATS * 4)

__global__ __launch_bounds__(256) void attn_kernel(float* __restrict__ out)
{
    extern __shared__ float sm[];
    float* Qs = sm;                     // 128*68
    float* Ks = Qs + 128 * QPAD;        // 128*68
    float* Vs = Ks + 128 * QPAD;        // 128*68
    float* Ps = Vs + 128 * QPAD;        // 128*132

    const int qb = blockIdx.x;
    const int h  = blockIdx.y;
    const int b  = blockIdx.z;
    const int tid = threadIdx.x;
    const int tx = tid & 15;
    const int ty = tid >> 4;

    const int q0 = qb * BM_A;
    const size_t base = (size_t)b * TSEQ * 3 * CDIM + (size_t)h * HS;
    const float* qkv = g_qkv;

    // load Q tile: 128 rows x 64 floats = 2048 float4, 8 per thread
#pragma unroll
    for (int it = 0; it < 8; it++) {
        const int idx = tid + it * 256;
        const int r  = idx >> 4;             // 0..127
        const int c4 = (idx & 15) << 2;      // 0..60
        *(float4*)(Qs + r * QPAD + c4) =
            *(const float4*)(qkv + base + (size_t)(q0 + r) * (3 * CDIM) + c4);
    }

    float O[8][4];
#pragma unroll
    for (int i = 0; i < 8; i++)
#pragma unroll
        for (int j = 0; j < 4; j++) O[i][j] = 0.0f;
    float mrow[8], lrow[8];
#pragma unroll
    for (int i = 0; i < 8; i++) { mrow[i] = -INFINITY; lrow[i] = 0.0f; }

    const float scale = 0.125f;  // 1/sqrt(64)

    for (int kb = 0; kb <= qb; kb++) {
        const int k0 = kb * BN_A;
        __syncthreads();   // protect Ks/Vs/Ps from previous iteration
        // load K and V tiles: 128 rows x 64 floats each
#pragma unroll
        for (int it = 0; it < 8; it++) {
            const int idx = tid + it * 256;
            const int r  = idx >> 4;
            const int c4 = (idx & 15) << 2;
            const size_t grow = base + (size_t)(k0 + r) * (3 * CDIM);
            *(float4*)(Ks + r * QPAD + c4) = *(const float4*)(qkv + grow + CDIM + c4);
            *(float4*)(Vs + r * QPAD + c4) = *(const float4*)(qkv + grow + 2 * CDIM + c4);
        }
        __syncthreads();

        // S = Q K^T (rows 8ty+i, cols tx+16j, j=0..7)
        float S[8][8];
#pragma unroll
        for (int i = 0; i < 8; i++)
#pragma unroll
            for (int j = 0; j < 8; j++) S[i][j] = 0.0f;

#pragma unroll 2
        for (int d = 0; d < 64; d += 4) {
            float4 qv[8];
#pragma unroll
            for (int i = 0; i < 8; i++)
                qv[i] = *(const float4*)(Qs + (8 * ty + i) * QPAD + d);
#pragma unroll
            for (int jj = 0; jj < 2; jj++) {
                float4 kv[4];
#pragma unroll
                for (int j = 0; j < 4; j++)
                    kv[j] = *(const float4*)(Ks + (tx + 16 * (4 * jj + j)) * QPAD + d);
#pragma unroll
                for (int i = 0; i < 8; i++)
#pragma unroll
                    for (int j = 0; j < 4; j++) {
                        float* s = &S[i][4 * jj + j];
                        *s = fmaf(qv[i].x, kv[j].x, *s);
                        *s = fmaf(qv[i].y, kv[j].y, *s);
                        *s = fmaf(qv[i].z, kv[j].z, *s);
                        *s = fmaf(qv[i].w, kv[j].w, *s);
                    }
            }
        }

        // scale + causal mask (diagonal block only; k0==q0 there)
        if (kb == qb) {
#pragma unroll
            for (int i = 0; i < 8; i++)
#pragma unroll
                for (int j = 0; j < 8; j++) {
                    if (tx + 16 * j > 8 * ty + i) S[i][j] = -INFINITY;
                    else                          S[i][j] *= scale;
                }
        } else {
#pragma unroll
            for (int i = 0; i < 8; i++)
#pragma unroll
                for (int j = 0; j < 8; j++) S[i][j] *= scale;
        }

        // online softmax per row (row shared by 16 tx-lanes = half-warp)
#pragma unroll
        for (int i = 0; i < 8; i++) {
            float mx = S[i][0];
#pragma unroll
            for (int j = 1; j < 8; j++) mx = fmaxf(mx, S[i][j]);
#pragma unroll
            for (int off = 8; off >= 1; off >>= 1)
                mx = fmaxf(mx, __shfl_xor_sync(0xffffffffu, mx, off));
            const float mnew  = fmaxf(mrow[i], mx);
            const float alpha = __expf(mrow[i] - mnew);
            float ls = 0.0f;
#pragma unroll
            for (int j = 0; j < 8; j++) {
                const float p = __expf(S[i][j] - mnew);
                S[i][j] = p;
                ls += p;
            }
#pragma unroll
            for (int off = 8; off >= 1; off >>= 1)
                ls += __shfl_xor_sync(0xffffffffu, ls, off);
            lrow[i] = lrow[i] * alpha + ls;
            mrow[i] = mnew;
#pragma unroll
            for (int j = 0; j < 4; j++) O[i][j] *= alpha;
            // write probabilities to smem
#pragma unroll
            for (int j = 0; j < 8; j++)
                Ps[(8 * ty + i) * PPAD + tx + 16 * j] = S[i][j];
        }
        __syncthreads();

        // O += P @ V  (rows 8ty+i, cols 4tx+j)
#pragma unroll 2
        for (int n = 0; n < 128; n += 4) {
            float4 pv[8];
#pragma unroll
            for (int i = 0; i < 8; i++)
                pv[i] = *(const float4*)(Ps + (8 * ty + i) * PPAD + n);
            float4 vv0 = *(const float4*)(Vs + (n + 0) * QPAD + 4 * tx);
            float4 vv1 = *(const float4*)(Vs + (n + 1) * QPAD + 4 * tx);
            float4 vv2 = *(const float4*)(Vs + (n + 2) * QPAD + 4 * tx);
            float4 vv3 = *(const float4*)(Vs + (n + 3) * QPAD + 4 * tx);
#pragma unroll
            for (int i = 0; i < 8; i++) {
                O[i][0] = fmaf(pv[i].x, vv0.x, O[i][0]);
                O[i][1] = fmaf(pv[i].x, vv0.y, O[i][1]);
                O[i][2] = fmaf(pv[i].x, vv0.z, O[i][2]);
                O[i][3] = fmaf(pv[i].x, vv0.w, O[i][3]);
                O[i][0] = fmaf(pv[i].y, vv1.x, O[i][0]);
                O[i][1] = fmaf(pv[i].y, vv1.y, O[i][1]);
                O[i][2] = fmaf(pv[i].y, vv1.z, O[i][2]);
                O[i][3] = fmaf(pv[i].y, vv1.w, O[i][3]);
                O[i][0] = fmaf(pv[i].z, vv2.x, O[i][0]);
                O[i][1] = fmaf(pv[i].z, vv2.y, O[i][1]);
                O[i][2] = fmaf(pv[i].z, vv2.z, O[i][2]);
                O[i][3] = fmaf(pv[i].z, vv2.w, O[i][3]);
                O[i][0] = fmaf(pv[i].w, vv3.x, O[i][0]);
                O[i][1] = fmaf(pv[i].w, vv3.y, O[i][1]);
                O[i][2] = fmaf(pv[i].w, vv3.z, O[i][2]);
                O[i][3] = fmaf(pv[i].w, vv3.w, O[i][3]);
            }
        }
    }

    // epilogue: divide by l and store. out[b][t][h*64 + d]
#pragma unroll
    for (int i = 0; i < 8; i++) {
        const float inv = 1.0f / lrow[i];
        float4 r;
        r.x = O[i][0] * inv; r.y = O[i][1] * inv;
        r.z = O[i][2] * inv; r.w = O[i][3] * inv;
        const size_t row = (size_t)b * TSEQ + q0 + 8 * ty + i;
        *(float4*)(out + row * CDIM + h * HS + 4 * tx) = r;
    }
}

// ---------------------------------------------------------------------------
extern "C" void kernel_launch(void* const* d_in, const int* in_sizes, int n_in,
                              void* d_out, int out_size)
{
    const float* x    = (const float*)d_in[0];
    const float* W    = (const float*)d_in[1];
    const float* bias = (const float*)d_in[2];
    float* out = (float*)d_out;

    (void)in_sizes; (void)n_in; (void)out_size;

    cudaFuncSetAttribute(attn_kernel,
                         cudaFuncAttributeMaxDynamicSharedMemorySize,
                         ATTN_SMEM_BYTES);

    // 1. split X into bf16 hi/lo
    split_x_kernel<<<(M_GEMM * K_GEMM / 4) / 256, 256>>>(x);
    // 2. transpose + split W into bf16 hi/lo  (Wt[n][k])
    split_w_kernel<<<dim3(N_GEMM / 32, K_GEMM / 32), dim3(32, 8)>>>(W);
    // 3. tensor-core (HMMA) GEMM -> g_qkv
    qkv_gemm_mma<<<dim3(N_GEMM / 128, M_GEMM / 128), 256>>>(bias);
    // 4. causal flash attention (8x8 microtile)
    dim3 agrid(TSEQ / BM_A, NHEAD, BATCH);
    attn_kernel<<<agrid, 256, ATTN_SMEM_BYTES>>>(out);
}

// round 15
// speedup vs baseline: 1.8986x; 1.5082x over previous
#include <cuda_runtime.h>
#include <cuda_bf16.h>
#include <cuda_fp16.h>
#include <math.h>
#include <stdint.h>

// Problem constants
#define BATCH   2
#define TSEQ    2048
#define CDIM    1024
#define NHEAD   16
#define HS      64
#define M_GEMM  (BATCH*TSEQ)   // 4096
#define N_GEMM  (3*CDIM)       // 3072
#define K_GEMM  CDIM           // 1024
#define KSPLIT  (3*K_GEMM)     // 3072

// Static device scratch
__device__ float         g_qkv [(size_t)M_GEMM * N_GEMM];   // 48 MB
__device__ __nv_bfloat16 g_Xhi [(size_t)M_GEMM * K_GEMM];
__device__ __nv_bfloat16 g_Xlo [(size_t)M_GEMM * K_GEMM];
__device__ __nv_bfloat16 g_Wthi[(size_t)N_GEMM * K_GEMM];
__device__ __nv_bfloat16 g_Wtlo[(size_t)N_GEMM * K_GEMM];
// fp16 hi/lo K and V^T for tensor-core attention (16B-aligned for uint4 access)
#define KVELEMS ((size_t)BATCH*NHEAD*TSEQ*HS)
__device__ __align__(16) __half g_Khi [KVELEMS];   // [bh][t][d]
__device__ __align__(16) __half g_Klo [KVELEMS];
__device__ __align__(16) __half g_Vthi[KVELEMS];   // [bh][d][t]
__device__ __align__(16) __half g_Vtlo[KVELEMS];

// ---------------------------------------------------------------------------
#define CP_ASYNC16(smem_u32, gptr) \
    asm volatile("cp.async.cg.shared.global [%0], [%1], 16;" \
                 :: "r"(smem_u32), "l"(gptr) : "memory")
#define CP_COMMIT() asm volatile("cp.async.commit_group;" ::: "memory")
#define CP_WAIT(n)  asm volatile("cp.async.wait_group %0;" :: "n"(n) : "memory")

__device__ __forceinline__ void mma_16816_bf16(
    float* c, uint32_t a0, uint32_t a1, uint32_t a2, uint32_t a3,
    uint32_t b0, uint32_t b1)
{
    asm volatile(
        "mma.sync.aligned.m16n8k16.row.col.f32.bf16.bf16.f32 "
        "{%0,%1,%2,%3}, {%4,%5,%6,%7}, {%8,%9}, {%0,%1,%2,%3};"
        : "+f"(c[0]), "+f"(c[1]), "+f"(c[2]), "+f"(c[3])
        : "r"(a0), "r"(a1), "r"(a2), "r"(a3), "r"(b0), "r"(b1));
}

__device__ __forceinline__ void mma_16816_f16(
    float* c, const uint32_t* a, uint32_t b0, uint32_t b1)
{
    asm volatile(
        "mma.sync.aligned.m16n8k16.row.col.f32.f16.f16.f32 "
        "{%0,%1,%2,%3}, {%4,%5,%6,%7}, {%8,%9}, {%0,%1,%2,%3};"
        : "+f"(c[0]), "+f"(c[1]), "+f"(c[2]), "+f"(c[3])
        : "r"(a[0]), "r"(a[1]), "r"(a[2]), "r"(a[3]), "r"(b0), "r"(b1));
}

// pack two floats into fp16x2 hi + fp16x2 lo (residual)
__device__ __forceinline__ void pack_hl(float x, float y, uint32_t& hi, uint32_t& lo)
{
    __half2 h = __floats2half2_rn(x, y);
    float2 back = __half22float2(h);
    __half2 l = __floats2half2_rn(x - back.x, y - back.y);
    hi = *(uint32_t*)&h;
    lo = *(uint32_t*)&l;
}

// ---------------------------------------------------------------------------
// fp32 -> bf16 hi/lo split kernels (unchanged, validated)
// ---------------------------------------------------------------------------
__global__ __launch_bounds__(256) void split_x_kernel(const float* __restrict__ X)
{
    const int idx = blockIdx.x * blockDim.x + threadIdx.x;
    float4 v = ((const float4*)X)[idx];
    __nv_bfloat16 h0 = __float2bfloat16(v.x), h1 = __float2bfloat16(v.y);
    __nv_bfloat16 h2 = __float2bfloat16(v.z), h3 = __float2bfloat16(v.w);
    __nv_bfloat16 l0 = __float2bfloat16(v.x - __bfloat162float(h0));
    __nv_bfloat16 l1 = __float2bfloat16(v.y - __bfloat162float(h1));
    __nv_bfloat16 l2 = __float2bfloat16(v.z - __bfloat162float(h2));
    __nv_bfloat16 l3 = __float2bfloat16(v.w - __bfloat162float(h3));
    __nv_bfloat162 p;
    p.x = h0; p.y = h1; ((__nv_bfloat162*)g_Xhi)[2 * idx]     = p;
    p.x = h2; p.y = h3; ((__nv_bfloat162*)g_Xhi)[2 * idx + 1] = p;
    p.x = l0; p.y = l1; ((__nv_bfloat162*)g_Xlo)[2 * idx]     = p;
    p.x = l2; p.y = l3; ((__nv_bfloat162*)g_Xlo)[2 * idx + 1] = p;
}

__global__ __launch_bounds__(256) void split_w_kernel(const float* __restrict__ W)
{
    __shared__ float ts[32][33];
    const int n0 = blockIdx.x * 32, k0 = blockIdx.y * 32;
    const int tx = threadIdx.x, ty = threadIdx.y;
#pragma unroll
    for (int j = 0; j < 4; j++)
        ts[ty + j * 8][tx] = W[(size_t)(k0 + ty + j * 8) * N_GEMM + n0 + tx];
    __syncthreads();
#pragma unroll
    for (int j = 0; j < 4; j++) {
        const float v = ts[tx][ty + j * 8];
        const __nv_bfloat16 h = __float2bfloat16(v);
        const __nv_bfloat16 l = __float2bfloat16(v - __bfloat162float(h));
        const size_t o = (size_t)(n0 + ty + j * 8) * K_GEMM + k0 + tx;
        g_Wthi[o] = h;
        g_Wtlo[o] = l;
    }
}

// ---------------------------------------------------------------------------
// bf16 split GEMM via mma.sync (unchanged, validated: rel_err 1.6e-5)
// ---------------------------------------------------------------------------
#define BKC 32
#define NCHUNK (KSPLIT / BKC)
#define APAD 40
#define NSTAGE 3

__global__ __launch_bounds__(256) void qkv_gemm_mma(const float* __restrict__ bias)
{
    __shared__ __align__(16) __nv_bfloat16 As[NSTAGE][128][APAD];
    __shared__ __align__(16) __nv_bfloat16 Bs[NSTAGE][128][APAD];

    const int tid  = threadIdx.x;
    const int warp = tid >> 5;
    const int lane = tid & 31;
    const int g    = lane >> 2;
    const int tg   = lane & 3;
    const int wm   = (warp >> 2) * 64;
    const int wn   = (warp & 3) * 32;
    const int brow = blockIdx.y;
    const int bcol = blockIdx.x;

    const int ldRow  = tid >> 2;
    const int ldCol8 = (tid & 3) * 8;

    float acc[4][4][4];
#pragma unroll
    for (int mi = 0; mi < 4; mi++)
#pragma unroll
        for (int ni = 0; ni < 4; ni++)
#pragma unroll
            for (int r = 0; r < 4; r++) acc[mi][ni][r] = 0.0f;

    const size_t aRowOff = (size_t)brow * 128 * K_GEMM;
    const size_t bRowOff = (size_t)bcol * 128 * K_GEMM;

    auto load_tile = [&](int c, int s) {
        const int kb  = c * BKC;
        const int reg = kb >> 10;
        const int ko  = kb & 1023;
        const __nv_bfloat16* Asrc = (reg == 2 ? g_Xlo  : g_Xhi ) + aRowOff + ko;
        const __nv_bfloat16* Bsrc = (reg == 1 ? g_Wtlo : g_Wthi) + bRowOff + ko;
#pragma unroll
        for (int it = 0; it < 2; it++) {
            const int r = ldRow + it * 64;
            CP_ASYNC16((uint32_t)__cvta_generic_to_shared(&As[s][r][ldCol8]),
                       Asrc + (size_t)r * K_GEMM + ldCol8);
            CP_ASYNC16((uint32_t)__cvta_generic_to_shared(&Bs[s][r][ldCol8]),
                       Bsrc + (size_t)r * K_GEMM + ldCol8);
        }
        CP_COMMIT();
    };

    load_tile(0, 0);
    load_tile(1, 1);

    for (int c = 0; c < NCHUNK; c++) {
        const int buf = c % NSTAGE;
        if (c + NSTAGE - 1 < NCHUNK) {
            load_tile(c + NSTAGE - 1, (c + NSTAGE - 1) % NSTAGE);
            CP_WAIT(NSTAGE - 1);
        } else if (c + 1 < NCHUNK) {
            CP_WAIT(1);
        } else {
            CP_WAIT(0);
        }
        __syncthreads();

#pragma unroll
        for (int ks = 0; ks < 2; ks++) {
            const int kc = tg * 2 + ks * 16;
            uint32_t a[4][4];
#pragma unroll
            for (int mi = 0; mi < 4; mi++) {
                const int r = wm + mi * 16 + g;
                a[mi][0] = *(const uint32_t*)&As[buf][r    ][kc];
                a[mi][1] = *(const uint32_t*)&As[buf][r + 8][kc];
                a[mi][2] = *(const uint32_t*)&As[buf][r    ][kc + 8];
                a[mi][3] = *(const uint32_t*)&As[buf][r + 8][kc + 8];
            }
            uint32_t b[4][2];
#pragma unroll
            for (int ni = 0; ni < 4; ni++) {
                const int r = wn + ni * 8 + g;
                b[ni][0] = *(const uint32_t*)&Bs[buf][r][kc];
                b[ni][1] = *(const uint32_t*)&Bs[buf][r][kc + 8];
            }
#pragma unroll
            for (int mi = 0; mi < 4; mi++)
#pragma unroll
                for (int ni = 0; ni < 4; ni++)
                    mma_16816_bf16(acc[mi][ni],
                                   a[mi][0], a[mi][1], a[mi][2], a[mi][3],
                                   b[ni][0], b[ni][1]);
        }
        __syncthreads();
    }

#pragma unroll
    for (int mi = 0; mi < 4; mi++) {
        const int row0 = brow * 128 + wm + mi * 16 + g;
#pragma unroll
        for (int ni = 0; ni < 4; ni++) {
            const int col0 = bcol * 128 + wn + ni * 8 + tg * 2;
            const float b0 = bias[col0], b1 = bias[col0 + 1];
            float2 v;
            v.x = acc[mi][ni][0] + b0;
            v.y = acc[mi][ni][1] + b1;
            *(float2*)(g_qkv + (size_t)row0 * N_GEMM + col0) = v;
            v.x = acc[mi][ni][2] + b0;
            v.y = acc[mi][ni][3] + b1;
            *(float2*)(g_qkv + (size_t)(row0 + 8) * N_GEMM + col0) = v;
        }
    }
}

// ---------------------------------------------------------------------------
// Convert K -> fp16 hi/lo [bh][t][d], V -> transposed fp16 hi/lo [bh][d][t].
// grid (T/64, NH, B), 256 threads; one 64-key block per CTA.
// ---------------------------------------------------------------------------
__global__ __launch_bounds__(256) void kv_convert_kernel()
{
    __shared__ __align__(16) float vs[64][68];   // 272B row stride, 16B-aligned
    const int kb = blockIdx.x, h = blockIdx.y, b = blockIdx.z;
    const int bh = b * NHEAD + h;
    const int k0 = kb * 64;
    const int tid = threadIdx.x;
    const int r = tid >> 2;            // 0..63
    const int c = (tid & 3) * 16;      // 0,16,32,48
    const size_t qbase = (size_t)b * TSEQ * 3 * CDIM + (size_t)h * HS;

    // K: direct convert + store
    {
        const float* src = g_qkv + qbase + (size_t)(k0 + r) * (3 * CDIM) + CDIM + c;
        const size_t o = ((size_t)bh * TSEQ + k0 + r) * HS + c;
#pragma unroll
        for (int i = 0; i < 4; i++) {
            float4 v = *(const float4*)(src + i * 4);
            uint32_t h0, l0, h1, l1;
            pack_hl(v.x, v.y, h0, l0);
            pack_hl(v.z, v.w, h1, l1);
            ((uint32_t*)(g_Khi + o))[i * 2]     = h0;
            ((uint32_t*)(g_Khi + o))[i * 2 + 1] = h1;
            ((uint32_t*)(g_Klo + o))[i * 2]     = l0;
            ((uint32_t*)(g_Klo + o))[i * 2 + 1] = l1;
        }
    }
    // V: stage fp32 tile, then transposed convert + store
    {
        const float* src = g_qkv + qbase + (size_t)(k0 + r) * (3 * CDIM) + 2 * CDIM + c;
#pragma unroll
        for (int i = 0; i < 4; i++)
            *(float4*)(&vs[r][c + i * 4]) = *(const float4*)(src + i * 4);
    }
    __syncthreads();
    {
        const int d = tid >> 2;
        const int ks = (tid & 3) * 16;
        const size_t o = ((size_t)bh * HS + d) * TSEQ + k0 + ks;
#pragma unroll
        for (int i = 0; i < 8; i++) {
            const float x = vs[ks + 2 * i][d];
            const float y = vs[ks + 2 * i + 1][d];
            uint32_t hh, ll;
            pack_hl(x, y, hh, ll);
            ((uint32_t*)(g_Vthi + o))[i] = hh;
            ((uint32_t*)(g_Vtlo + o))[i] = ll;
        }
    }
}

// ---------------------------------------------------------------------------
// Tensor-core causal flash attention (mma.sync f16, hi/lo 3-term).
// BM=128 (8 warps x 16 rows), BN=64, HS=64. grid (T/128, NH, B), 256 thr.
// ---------------------------------------------------------------------------
#define KSTR 72   // smem row stride in halves (144B, 16B-divisible)

__global__ __launch_bounds__(256) void attn_mma_kernel(float* __restrict__ out)
{
    __shared__ __align__(16) __half sKh[64 * KSTR], sKl[64 * KSTR];
    __shared__ __align__(16) __half sVh[64 * KSTR], sVl[64 * KSTR];

    const int qb = blockIdx.x, h = blockIdx.y, b = blockIdx.z;
    const int bh = b * NHEAD + h;
    const int tid = threadIdx.x;
    const int w = tid >> 5;
    const int lane = tid & 31;
    const int g  = lane >> 2;
    const int tg = lane & 3;
    const int q0 = qb * 128;
    const int r0 = q0 + 16 * w + g;   // first row of this thread
    const int r1 = r0 + 8;            // second row

    // Q fragments (fp16 hi/lo) from fp32 g_qkv, once per CTA
    uint32_t qh[4][4], ql[4][4];
    {
        const float* qb_ptr = g_qkv + (size_t)b * TSEQ * 3 * CDIM + (size_t)h * HS;
        const float* p0 = qb_ptr + (size_t)r0 * (3 * CDIM);
        const float* p1 = qb_ptr + (size_t)r1 * (3 * CDIM);
#pragma unroll
        for (int s = 0; s < 4; s++) {
            float2 v0 = *(const float2*)(p0 + 16 * s + 2 * tg);
            float2 v1 = *(const float2*)(p1 + 16 * s + 2 * tg);
            float2 v2 = *(const float2*)(p0 + 16 * s + 8 + 2 * tg);
            float2 v3 = *(const float2*)(p1 + 16 * s + 8 + 2 * tg);
            pack_hl(v0.x, v0.y, qh[s][0], ql[s][0]);
            pack_hl(v1.x, v1.y, qh[s][1], ql[s][1]);
            pack_hl(v2.x, v2.y, qh[s][2], ql[s][2]);
            pack_hl(v3.x, v3.y, qh[s][3], ql[s][3]);
        }
    }

    float co[8][4];
#pragma unroll
    for (int j = 0; j < 8; j++)
#pragma unroll
        for (int r = 0; r < 4; r++) co[j][r] = 0.0f;
    float m0 = -INFINITY, m1 = -INFINITY, l0 = 0.0f, l1 = 0.0f;

    const int nkb = 2 * qb + 2;
    const int ldr = tid >> 2;          // tile-load row
    const int ldc = (tid & 3) * 16;    // tile-load col (halves)

    for (int kb = 0; kb < nkb; kb++) {
        const int k0 = kb * 64;
        __syncthreads();
        // fill K/V tiles (fp16 hi/lo, V already transposed)
        {
            const size_t ko = ((size_t)bh * TSEQ + k0 + ldr) * HS + ldc;
            *(uint4*)(sKh + ldr * KSTR + ldc)     = *(const uint4*)(g_Khi + ko);
            *(uint4*)(sKh + ldr * KSTR + ldc + 8) = *(const uint4*)(g_Khi + ko + 8);
            *(uint4*)(sKl + ldr * KSTR + ldc)     = *(const uint4*)(g_Klo + ko);
            *(uint4*)(sKl + ldr * KSTR + ldc + 8) = *(const uint4*)(g_Klo + ko + 8);
            const size_t vo = ((size_t)bh * HS + ldr) * TSEQ + k0 + ldc;
            *(uint4*)(sVh + ldr * KSTR + ldc)     = *(const uint4*)(g_Vthi + vo);
            *(uint4*)(sVh + ldr * KSTR + ldc + 8) = *(const uint4*)(g_Vthi + vo + 8);
            *(uint4*)(sVl + ldr * KSTR + ldc)     = *(const uint4*)(g_Vtlo + vo);
            *(uint4*)(sVl + ldr * KSTR + ldc + 8) = *(const uint4*)(g_Vtlo + vo + 8);
        }
        __syncthreads();

        if (k0 <= q0 + 16 * w + 15) {   // warp has unmasked work in this block
            // --- S = Q K^T (fp32 accum), 3 hi/lo terms ---
            float cs[8][4];
#pragma unroll
            for (int j = 0; j < 8; j++)
#pragma unroll
                for (int r = 0; r < 4; r++) cs[j][r] = 0.0f;

#pragma unroll
            for (int s = 0; s < 4; s++) {
#pragma unroll
                for (int j = 0; j < 8; j++) {
                    const int kr = (8 * j + g) * KSTR + 16 * s + 2 * tg;
                    const uint32_t bh0 = *(const uint32_t*)(sKh + kr);
                    const uint32_t bh1 = *(const uint32_t*)(sKh + kr + 8);
                    const uint32_t bl0 = *(const uint32_t*)(sKl + kr);
                    const uint32_t bl1 = *(const uint32_t*)(sKl + kr + 8);
                    mma_16816_f16(cs[j], qh[s], bh0, bh1);
                    mma_16816_f16(cs[j], qh[s], bl0, bl1);
                    mma_16816_f16(cs[j], ql[s], bh0, bh1);
                }
            }

            // --- mask + scale ---
            const float scale = 0.125f;
            if (k0 + 63 > r0) {
#pragma unroll
                for (int j = 0; j < 8; j++) {
                    const int c0 = k0 + 8 * j + 2 * tg;
                    const int c1 = c0 + 1;
                    cs[j][0] = (c0 > r0) ? -INFINITY : cs[j][0] * scale;
                    cs[j][1] = (c1 > r0) ? -INFINITY : cs[j][1] * scale;
                    cs[j][2] = (c0 > r1) ? -INFINITY : cs[j][2] * scale;
                    cs[j][3] = (c1 > r1) ? -INFINITY : cs[j][3] * scale;
                }
            } else {
#pragma unroll
                for (int j = 0; j < 8; j++)
#pragma unroll
                    for (int r = 0; r < 4; r++) cs[j][r] *= scale;
            }

            // --- online softmax (rows r0: cs[j][0,1]; r1: cs[j][2,3]) ---
            float mx0 = -INFINITY, mx1 = -INFINITY;
#pragma unroll
            for (int j = 0; j < 8; j++) {
                mx0 = fmaxf(mx0, fmaxf(cs[j][0], cs[j][1]));
                mx1 = fmaxf(mx1, fmaxf(cs[j][2], cs[j][3]));
            }
            mx0 = fmaxf(mx0, __shfl_xor_sync(0xffffffffu, mx0, 1));
            mx0 = fmaxf(mx0, __shfl_xor_sync(0xffffffffu, mx0, 2));
            mx1 = fmaxf(mx1, __shfl_xor_sync(0xffffffffu, mx1, 1));
            mx1 = fmaxf(mx1, __shfl_xor_sync(0xffffffffu, mx1, 2));
            const float mn0 = fmaxf(m0, mx0);
            const float mn1 = fmaxf(m1, mx1);
            const float a0f = __expf(m0 - mn0);
            const float a1f = __expf(m1 - mn1);
            float s0 = 0.0f, s1 = 0.0f;
#pragma unroll
            for (int j = 0; j < 8; j++) {
                cs[j][0] = __expf(cs[j][0] - mn0);
                cs[j][1] = __expf(cs[j][1] - mn0);
                cs[j][2] = __expf(cs[j][2] - mn1);
                cs[j][3] = __expf(cs[j][3] - mn1);
                s0 += cs[j][0] + cs[j][1];
                s1 += cs[j][2] + cs[j][3];
            }
            s0 += __shfl_xor_sync(0xffffffffu, s0, 1);
            s0 += __shfl_xor_sync(0xffffffffu, s0, 2);
            s1 += __shfl_xor_sync(0xffffffffu, s1, 1);
            s1 += __shfl_xor_sync(0xffffffffu, s1, 2);
            l0 = l0 * a0f + s0;
            l1 = l1 * a1f + s1;
            m0 = mn0;
            m1 = mn1;
#pragma unroll
            for (int j = 0; j < 8; j++) {
                co[j][0] *= a0f; co[j][1] *= a0f;
                co[j][2] *= a1f; co[j][3] *= a1f;
            }

            // --- P fragments (C layout -> A layout, hi/lo) ---
            uint32_t ph[4][4], pl[4][4];
#pragma unroll
            for (int s = 0; s < 4; s++) {
                pack_hl(cs[2 * s][0],     cs[2 * s][1],     ph[s][0], pl[s][0]);
                pack_hl(cs[2 * s][2],     cs[2 * s][3],     ph[s][1], pl[s][1]);
                pack_hl(cs[2 * s + 1][0], cs[2 * s + 1][1], ph[s][2], pl[s][2]);
                pack_hl(cs[2 * s + 1][2], cs[2 * s + 1][3], ph[s][3], pl[s][3]);
            }

            // --- O += P V (3 hi/lo terms) ---
#pragma unroll
            for (int s = 0; s < 4; s++) {
#pragma unroll
                for (int j = 0; j < 8; j++) {
                    const int vr = (8 * j + g) * KSTR + 16 * s + 2 * tg;
                    const uint32_t bh0 = *(const uint32_t*)(sVh + vr);
                    const uint32_t bh1 = *(const uint32_t*)(sVh + vr + 8);
                    const uint32_t bl0 = *(const uint32_t*)(sVl + vr);
                    const uint32_t bl1 = *(const uint32_t*)(sVl + vr + 8);
                    mma_16816_f16(co[j], ph[s], bh0, bh1);
                    mma_16816_f16(co[j], ph[s], bl0, bl1);
                    mma_16816_f16(co[j], pl[s], bh0, bh1);
                }
            }
        }
    }

    // epilogue: divide by l, store fp32
    const float i0 = 1.0f / l0;
    const float i1 = 1.0f / l1;
    float* ob = out + (size_t)b * TSEQ * CDIM + (size_t)h * HS;
#pragma unroll
    for (int j = 0; j < 8; j++) {
        float2 v;
        v.x = co[j][0] * i0; v.y = co[j][1] * i0;
        *(float2*)(ob + (size_t)r0 * CDIM + 8 * j + 2 * tg) = v;
        v.x = co[j][2] * i1; v.y = co[j][3] * i1;
        *(float2*)(ob + (size_t)r1 * CDIM + 8 * j + 2 * tg) = v;
    }
}

// ---------------------------------------------------------------------------
extern "C" void kernel_launch(void* const* d_in, const int* in_sizes, int n_in,
                              void* d_out, int out_size)
{
    const float* x    = (const float*)d_in[0];
    const float* W    = (const float*)d_in[1];
    const float* bias = (const float*)d_in[2];
    float* out = (float*)d_out;

    (void)in_sizes; (void)n_in; (void)out_size;

    // 1. split X into bf16 hi/lo
    split_x_kernel<<<(M_GEMM * K_GEMM / 4) / 256, 256>>>(x);
    // 2. transpose + split W into bf16 hi/lo
    split_w_kernel<<<dim3(N_GEMM / 32, K_GEMM / 32), dim3(32, 8)>>>(W);
    // 3. HMMA GEMM -> g_qkv
    qkv_gemm_mma<<<dim3(N_GEMM / 128, M_GEMM / 128), 256>>>(bias);
    // 4. K/V fp16 hi/lo conversion (V transposed)
    kv_convert_kernel<<<dim3(TSEQ / 64, NHEAD, BATCH), 256>>>();
    // 5. tensor-core causal flash attention
    attn_mma_kernel<<<dim3(TSEQ / 128, NHEAD, BATCH), 256>>>(out);
}